// round 1
// baseline (speedup 1.0000x reference)
#include <cuda_runtime.h>
#include <cuda_bf16.h>

// h_new[n, j] = h_prev[n, j] + sum_k W[Z[n]][j][k] * m_curr[n][k]
// N = 16384 nodes, D = 128 hidden, S = 119 species, atom_types sorted.
//
// Strategy: block = 64 nodes, 256 threads. Exploit sortedness: per same-species
// segment, each thread caches a 64-float half-row of W[z] in REGISTERS and
// reuses it across all nodes of the segment (avg run length ~138). m tile in
// shared memory, broadcast LDS.128 in the inner loop -> FFMA-pipe bound.

#define N_NODES  16384
#define D        128
#define NB       64     // nodes per block
#define NT       8      // node batch per inner pass
#define THREADS  256

__global__ void __launch_bounds__(THREADS, 2)
element_update_kernel(const float* __restrict__ h_prev,
                      const float* __restrict__ m_curr,
                      const int*   __restrict__ atom_types,
                      const float* __restrict__ weight,
                      float*       __restrict__ out)
{
    __shared__ float m_s[NB + NT][D];   // padded: batch may overrun segment end
    __shared__ float red[NT][D];        // cross-half reduction buffer
    __shared__ int   seg_end_s;

    const int t  = threadIdx.x;
    const int j  = t & (D - 1);         // output row index 0..127
    const int h  = t >> 7;              // half: 0 -> k in [0,64), 1 -> k in [64,128)
    const int n0 = blockIdx.x * NB;

    // Load m tile (coalesced float4): NB*D floats
    {
        const float4* src = (const float4*)(m_curr + (long)n0 * D);
        float4* dst = (float4*)(&m_s[0][0]);
        #pragma unroll 4
        for (int i = t; i < NB * D / 4; i += THREADS) dst[i] = src[i];
    }
    __syncthreads();

    int s = 0;
    while (s < NB) {
        const int z = atom_types[n0 + s];

        // thread 0: binary search for end of this species run (types are sorted)
        if (t == 0) {
            int lo = n0 + s, hi = N_NODES;
            while (lo < hi) {
                int mid = (lo + hi) >> 1;
                if (atom_types[mid] <= z) lo = mid + 1; else hi = mid;
            }
            int e = lo - n0;
            seg_end_s = e < NB ? e : NB;
        }
        __syncthreads();
        const int e = seg_end_s;

        // Cache this thread's 64-float half-row of W[z] in registers.
        // weight layout: (S, D*D) row-major => W[z][j][k] at z*D*D + j*D + k
        float w[64];
        {
            const float4* wp =
                (const float4*)(weight + ((long)z * D * D + (long)j * D + h * 64));
            #pragma unroll
            for (int i = 0; i < 16; i++) ((float4*)w)[i] = wp[i];
        }

        for (int nb = s; nb < e; nb += NT) {
            float acc[NT];
            #pragma unroll
            for (int n = 0; n < NT; n++) acc[n] = 0.0f;

            // Main FFMA loop: per (kk, n): 1 broadcast LDS.128 + 4 FFMA
            #pragma unroll
            for (int kk = 0; kk < 16; kk++) {
                #pragma unroll
                for (int n = 0; n < NT; n++) {
                    float4 m4 = ((const float4*)&m_s[nb + n][h * 64])[kk];
                    acc[n] = fmaf(w[4 * kk + 0], m4.x, acc[n]);
                    acc[n] = fmaf(w[4 * kk + 1], m4.y, acc[n]);
                    acc[n] = fmaf(w[4 * kk + 2], m4.z, acc[n]);
                    acc[n] = fmaf(w[4 * kk + 3], m4.w, acc[n]);
                }
            }

            // Reduce halves: h==1 publishes, h==0 combines + adds h_prev + stores
            if (h == 1) {
                #pragma unroll
                for (int n = 0; n < NT; n++) red[n][j] = acc[n];
            }
            __syncthreads();
            if (h == 0) {
                #pragma unroll
                for (int n = 0; n < NT; n++) {
                    int node = nb + n;
                    if (node < e) {
                        long idx = (long)(n0 + node) * D + j;
                        out[idx] = h_prev[idx] + acc[n] + red[n][j];
                    }
                }
            }
            __syncthreads();   // red reuse / seg_end_s reuse barrier
        }
        s = e;
    }
}

extern "C" void kernel_launch(void* const* d_in, const int* in_sizes, int n_in,
                              void* d_out, int out_size)
{
    const float* h_prev     = (const float*)d_in[0];
    const float* m_curr     = (const float*)d_in[1];
    const int*   atom_types = (const int*)  d_in[2];
    const float* weight     = (const float*)d_in[3];
    float*       out        = (float*)d_out;

    dim3 grid(N_NODES / NB);   // 256 blocks, <=2 resident/SM -> single wave
    dim3 block(THREADS);
    element_update_kernel<<<grid, block>>>(h_prev, m_curr, atom_types, weight, out);
}